// round 9
// baseline (speedup 1.0000x reference)
#include <cuda_runtime.h>
#include <math.h>

#define B_N    256
#define T_PAST 20
#define T_FUT  30
#define NT     256

// ---- shared memory layout (float indices) ----
#define SM_WT1   0        // 4*32*36  conv1 [kk][co][ci] stride 36
#define SM_WT2   4608
#define SM_WT3   9216
#define SM_WT0   13824    // 256
#define SM_CB    14080    // 128
#define SM_DWIH  14208    // 96*36
#define SM_DWHH  17664    // 96*36
#define SM_EWHH  21120    // 96*36
#define SM_WC    24576    // 128
#define SM_BC    24704    // 4
#define SM_A0    24708    // 800
#define SM_A1    25508    // 512
#define SM_A2    26020    // 288
#define SM_LID   26308    // 72
#define SM_X     26380    // 36
#define SM_H     26416    // 32
#define SM_GI    26448    // 96
#define SM_GH    26544    // 96
#define SM_Y     26640    // 4
#define SM_PP    26644    // 40
#define SM_ZB    26684    // 60
#define SM_EWIH  26744    // 192
#define SM_EBIH  26936    // 96
#define SM_EBHH  27032    // 96
#define SM_DBIH  27128    // 96
#define SM_DBHH  27224    // 96
#define SM_LD    27320    // 2
#define SM_TOTAL 27322
#define SMEM_BYTES (SM_TOTAL * 4)

typedef unsigned long long ull;

#define BARS(id, cnt) asm volatile("bar.sync %0, %1;" :: "n"(id), "n"(cnt) : "memory")

__device__ __forceinline__ void ffma2(ull& d, ull a, ull b) {
    asm("fma.rn.f32x2 %0, %1, %2, %0;" : "+l"(d) : "l"(a), "l"(b));
}
__device__ __forceinline__ float hsum2(ull v) {
    float lo, hi;
    asm("mov.b64 {%0,%1}, %2;" : "=f"(lo), "=f"(hi) : "l"(v));
    return lo + hi;
}
__device__ __forceinline__ float fexp2_(float x) {
    float r; asm("ex2.approx.f32 %0, %1;" : "=f"(r) : "f"(x)); return r;
}
__device__ __forceinline__ float flg2_(float x) {
    float r; asm("lg2.approx.f32 %0, %1;" : "=f"(r) : "f"(x)); return r;
}
__device__ __forceinline__ float frcp_(float x) {
    float r; asm("rcp.approx.f32 %0, %1;" : "=f"(r) : "f"(x)); return r;
}
__device__ __forceinline__ float ftanh_(float x) {
    float r; asm("tanh.approx.f32 %0, %1;" : "=f"(r) : "f"(x)); return r;
}
#define LOG2E 1.4426950408889634f
#define LN2   0.6931471805599453f
__device__ __forceinline__ float fsig_(float x) {
    return frcp_(1.f + fexp2_(-LOG2E * x));
}
__device__ __forceinline__ float flogf_(float x) { return flg2_(x) * LN2; }
__device__ __forceinline__ float fsoftplus_(float x) {
    return (x > 20.f) ? x : flg2_(1.f + fexp2_(LOG2E * x)) * LN2;
}

// One conv tile: CPW cells starting at cb, lane = output channel.
template <int OS, int IS, int CPW>
__device__ __forceinline__ void conv_tile(const float* __restrict__ ain,
                                          float* __restrict__ aout,
                                          const float* __restrict__ wT,
                                          const float* __restrict__ bias,
                                          int cb, int fy, int fx, int lane)
{
    int rr[CPW], xx[CPW];
    #pragma unroll
    for (int c = 0; c < CPW; ++c) { rr[c] = (cb + c) / OS; xx[c] = (cb + c) % OS; }

    ull acc[CPW][2];
    #pragma unroll
    for (int c = 0; c < CPW; ++c) { acc[c][0] = 0ULL; acc[c][1] = 0ULL; }

    #pragma unroll
    for (int kk = 0; kk < 4; ++kk) {
        const int kh = kk >> 1, kw = kk & 1;
        const ulonglong2* wp = (const ulonglong2*)(wT + (kk * 32 + lane) * 36);
        const ulonglong2* ap[CPW];
        #pragma unroll
        for (int c = 0; c < CPW; ++c)
            ap[c] = (const ulonglong2*)(ain + ((rr[c] + kh) * IS + (xx[c] + kw)) * 32);
        #pragma unroll
        for (int q = 0; q < 8; ++q) {
            ulonglong2 wv = wp[q];
            #pragma unroll
            for (int c = 0; c < CPW; ++c) {
                ulonglong2 av = ap[c][q];
                ffma2(acc[c][0], av.x, wv.x);
                ffma2(acc[c][1], av.y, wv.y);
            }
        }
    }
    const float bl = bias[lane];
    #pragma unroll
    for (int c = 0; c < CPW; ++c) {
        float o = hsum2(acc[c][0]) + hsum2(acc[c][1]) + bl;
        o = fmaxf(o, 0.f);
        if (fy + rr[c] > 99 || fx + xx[c] > 99) o = 0.f;
        aout[(cb + c) * 32 + lane] = o;
    }
}

extern __shared__ float sm[];

__global__ void __launch_bounds__(NT, 2)
r2p2_kernel(const float* __restrict__ z,
            const float* __restrict__ pp,
            const float* __restrict__ lidar,
            const float* __restrict__ c0w, const float* __restrict__ c0b,
            const float* __restrict__ c1w, const float* __restrict__ c1b,
            const float* __restrict__ c2w, const float* __restrict__ c2b,
            const float* __restrict__ c3w, const float* __restrict__ c3b,
            const float* __restrict__ ewih, const float* __restrict__ ewhh,
            const float* __restrict__ ebih, const float* __restrict__ ebhh,
            const float* __restrict__ dwih, const float* __restrict__ dwhh,
            const float* __restrict__ dbih, const float* __restrict__ dbhh,
            const float* __restrict__ w1, const float* __restrict__ b1,
            const float* __restrict__ w2, const float* __restrict__ b2,
            float* __restrict__ out)
{
    const int b = blockIdx.x;
    const int tid = threadIdx.x;
    const int wid = tid >> 5, lane = tid & 31;

    float* WT1 = sm + SM_WT1;  float* WT2 = sm + SM_WT2;  float* WT3 = sm + SM_WT3;
    float* WT0 = sm + SM_WT0;  float* CB  = sm + SM_CB;
    float* DWIH = sm + SM_DWIH; float* DWHH = sm + SM_DWHH; float* EWHH = sm + SM_EWHH;
    float* WC = sm + SM_WC;    float* BC = sm + SM_BC;
    float* A0 = sm + SM_A0;  float* A1 = sm + SM_A1;  float* A2 = sm + SM_A2;
    float* LID = sm + SM_LID; float* X = sm + SM_X;  float* H = sm + SM_H;
    float* GI = sm + SM_GI;   float* GH = sm + SM_GH;
    float* Y  = sm + SM_Y;    float* PP = sm + SM_PP; float* ZB = sm + SM_ZB;
    float* EWIH = sm + SM_EWIH; float* EBIH = sm + SM_EBIH; float* EBHH = sm + SM_EBHH;
    float* DBIH = sm + SM_DBIH; float* DBHH = sm + SM_DBHH;
    float* LD = sm + SM_LD;

    // ---- setup: weight transposes + fused MLP collapse ----
    {
        const float* srcs[3] = { c1w, c2w, c3w };
        float* dsts[3] = { WT1, WT2, WT3 };
        #pragma unroll
        for (int l = 0; l < 3; ++l) {
            const float* s = srcs[l]; float* d = dsts[l];
            for (int idx = tid; idx < 4096; idx += NT) {
                int co = idx & 31, ci = (idx >> 5) & 31, kk = idx >> 10;
                d[(kk * 32 + co) * 36 + ci] = s[idx];
            }
        }
        for (int idx = tid; idx < 256; idx += NT) {
            int co = idx & 31, ci = (idx >> 5) & 1, kk = idx >> 6;
            WT0[(kk * 32 + co) * 2 + ci] = c0w[idx];
        }
    }
    if (tid < 32) {
        CB[tid] = c0b[tid]; CB[32 + tid] = c1b[tid];
        CB[64 + tid] = c2b[tid]; CB[96 + tid] = c3b[tid];
    }
    for (int idx = tid; idx < 96 * 34; idx += NT) {
        int j = idx / 34, k = idx % 34;
        DWIH[j * 36 + k] = dwih[idx];
    }
    for (int idx = tid; idx < 96 * 32; idx += NT) {
        int j = idx >> 5, k = idx & 31;
        DWHH[j * 36 + k] = dwhh[idx];
        EWHH[j * 36 + k] = ewhh[idx];
    }
    if (tid < 96) {
        EWIH[tid * 2] = ewih[tid * 2]; EWIH[tid * 2 + 1] = ewih[tid * 2 + 1];
        EBIH[tid] = ebih[tid]; EBHH[tid] = ebhh[tid];
        DBIH[tid] = dbih[tid]; DBHH[tid] = dbhh[tid];
    }
    // Wc = W2@W1 (threads 0..127), bc = W2@b1+b2 (threads 128..255)
    if (tid < 128) {
        int o = tid >> 5, i = tid & 31;
        const float* w2r = w2 + o * 512;
        float a0 = 0.f, a1 = 0.f;
        for (int k = 0; k < 512; k += 2) {
            a0 = fmaf(w2r[k + 0], w1[(k + 0) * 32 + i], a0);
            a1 = fmaf(w2r[k + 1], w1[(k + 1) * 32 + i], a1);
        }
        WC[tid] = a0 + a1;
    } else {
        int o = (tid - 128) >> 5, l = tid & 31;
        float acc = 0.f;
        for (int k = l; k < 512; k += 32) acc = fmaf(w2[o * 512 + k], b1[k], acc);
        #pragma unroll
        for (int off = 16; off; off >>= 1)
            acc += __shfl_xor_sync(0xffffffffu, acc, off);
        if (l == 0) BC[o] = acc + b2[o];
    }
    if (tid < 40) PP[tid] = pp[b * (T_PAST * 2) + tid];
    if (tid < 60) ZB[tid] = z[b * (T_FUT * 2) + tid];
    if (tid < 32) H[tid] = 0.f;
    if (tid < 2) {
        Y[tid]     = pp[(b * T_PAST + 19) * 2 + tid];   // y_{t-1}
        Y[2 + tid] = pp[(b * T_PAST + 18) * 2 + tid];   // y_{t-2}
    }
    __syncthreads();

    // ---- encoder GRU: 20 steps, entirely in warps 0-2 (named barrier 3) ----
    if (tid < 96) {
        for (int t = 0; t < T_PAST; ++t) {
            float x0 = PP[t * 2], x1 = PP[t * 2 + 1];
            float gi = EBIH[tid] + x0 * EWIH[tid * 2] + x1 * EWIH[tid * 2 + 1];
            ull g0 = 0ULL, g1 = 0ULL;
            const ulonglong2* wr = (const ulonglong2*)(EWHH + tid * 36);
            const ulonglong2* hp = (const ulonglong2*)H;
            #pragma unroll
            for (int k = 0; k < 8; ++k) {
                ulonglong2 wv = wr[k];
                ulonglong2 hv = hp[k];
                ffma2(g0, hv.x, wv.x);
                ffma2(g1, hv.y, wv.y);
            }
            GI[tid] = gi;
            GH[tid] = EBHH[tid] + hsum2(g0) + hsum2(g1);
            BARS(3, 96);
            if (tid < 32) {
                float r  = fsig_(GI[tid] + GH[tid]);
                float zg = fsig_(GI[32 + tid] + GH[32 + tid]);
                float n  = ftanh_(GI[64 + tid] + r * GH[64 + tid]);
                H[tid] = (1.f - zg) * n + zg * H[tid];
            }
            BARS(3, 96);
        }
    }
    __syncthreads();

    // ---- decoder: 30 autoregressive steps ----
    float logdet = 0.f;   // accumulated in tid 128,129 (warp 4 lanes 0,1)
    for (int t = 0; t < T_FUT; ++t) {
        if (tid < 128) {
            // ===== group A: conv pipeline (warps 0-3, named barrier 1) =====
            float q0c = Y[0], q1c = Y[1];
            float f0 = fminf(fmaxf(floorf(q0c), 0.f), 98.f);
            float f1 = fminf(fmaxf(floorf(q1c), 0.f), 98.f);
            const int fy = (int)f0, fx = (int)f1;

            if (tid < 72) {
                int rr = tid / 12, cc = (tid % 12) >> 1, ci = tid & 1;
                int gy = fy + rr, gx = fx + cc;
                float v = 0.f;
                if (gy < 100 && gx < 100)
                    v = lidar[((b * 100 + gy) * 100 + gx) * 2 + ci];
                LID[tid] = v;
            }
            BARS(1, 128);

            // layer0: 800 outputs over 128 threads
            #pragma unroll
            for (int it = 0; it < 7; ++it) {
                int idx = tid + (it << 7);
                if (idx < 800) {
                    int co = idx & 31, cell = idx >> 5;
                    int r = cell / 5, c = cell % 5;
                    ull acc = 0ULL;
                    #pragma unroll
                    for (int kk = 0; kk < 4; ++kk) {
                        int kh = kk >> 1, kw = kk & 1;
                        ull lv = *(const ull*)(LID + ((r + kh) * 6 + (c + kw)) * 2);
                        ull wv = *(const ull*)(WT0 + (kk * 32 + co) * 2);
                        ffma2(acc, lv, wv);
                    }
                    float o = fmaxf(hsum2(acc) + CB[co], 0.f);
                    if (fy + r > 99 || fx + c > 99) o = 0.f;
                    A0[cell * 32 + co] = o;
                }
            }
            BARS(1, 128);

            conv_tile<4, 5, 4>(A0, A1, WT1, CB + 32, wid * 4, fy, fx, lane);
            BARS(1, 128);

            if (wid < 3)
                conv_tile<3, 4, 3>(A1, A2, WT2, CB + 64, wid * 3, fy, fx, lane);
            BARS(1, 128);

            if (wid == 0) {
                float ay = fminf(fmaxf(q0c - f0, 0.f), 1.f);
                float ax = fminf(fmaxf(q1c - f1, 0.f), 1.f);
                ull acc[4][2];
                #pragma unroll
                for (int c = 0; c < 4; ++c) { acc[c][0] = 0ULL; acc[c][1] = 0ULL; }
                #pragma unroll
                for (int kk = 0; kk < 4; ++kk) {
                    const int kh = kk >> 1, kw = kk & 1;
                    const ulonglong2* wp = (const ulonglong2*)(WT3 + (kk * 32 + lane) * 36);
                    #pragma unroll
                    for (int q = 0; q < 8; ++q) {
                        ulonglong2 wv = wp[q];
                        #pragma unroll
                        for (int c = 0; c < 4; ++c) {
                            int r = c >> 1, x = c & 1;
                            const ulonglong2* ap =
                                (const ulonglong2*)(A2 + ((r + kh) * 3 + (x + kw)) * 32);
                            ulonglong2 av = ap[q];
                            ffma2(acc[c][0], av.x, wv.x);
                            ffma2(acc[c][1], av.y, wv.y);
                        }
                    }
                }
                const float bl = CB[96 + lane];
                float o[4];
                #pragma unroll
                for (int c = 0; c < 4; ++c) {
                    int r = c >> 1, x = c & 1;
                    float v = hsum2(acc[c][0]) + hsum2(acc[c][1]) + bl;
                    v = fmaxf(v, 0.f);
                    if (fy + r > 99 || fx + x > 99) v = 0.f;
                    o[c] = v;
                }
                float top = o[0] + ax * (o[1] - o[0]);
                float bot = o[2] + ax * (o[3] - o[2]);
                X[2 + lane] = top + ay * (bot - top);
                if (lane < 2) X[lane] = Y[lane];
            }
        } else if (tid < 224) {
            // ===== group B: GH matvec concurrent with the conv pyramid =====
            int j = tid - 128;
            ull g0 = 0ULL, g1 = 0ULL;
            const ulonglong2* hr = (const ulonglong2*)(DWHH + j * 36);
            const ulonglong2* hp = (const ulonglong2*)H;
            #pragma unroll
            for (int k = 0; k < 8; ++k) {
                ulonglong2 wv = hr[k];
                ulonglong2 hv = hp[k];
                ffma2(g0, hv.x, wv.x);
                ffma2(g1, hv.y, wv.y);
            }
            GH[j] = DBHH[j] + hsum2(g0) + hsum2(g1);
        }
        __syncthreads();   // X + GH ready

        if (tid >= 128 && tid < 224) {
            int j = tid - 128;
            // GI matvec
            ull a0 = 0ULL, a1 = 0ULL;
            const ulonglong2* wr = (const ulonglong2*)(DWIH + j * 36);
            const ulonglong2* xp = (const ulonglong2*)X;
            #pragma unroll
            for (int k = 0; k < 8; ++k) {
                ulonglong2 wv = wr[k];
                ulonglong2 xv = xp[k];
                ffma2(a0, xv.x, wv.x);
                ffma2(a1, xv.y, wv.y);
            }
            ull wl = *(const ull*)(DWIH + j * 36 + 32);
            ull xl = *(const ull*)(X + 32);
            ffma2(a0, xl, wl);
            GI[j] = DBIH[j] + hsum2(a0) + hsum2(a1);
            BARS(2, 96);

            if (j < 32) {   // warp 4: hidden update + head + y-update
                float r  = fsig_(GI[j] + GH[j]);
                float zg = fsig_(GI[32 + j] + GH[32 + j]);
                float n  = ftanh_(GI[64 + j] + r * GH[64 + j]);
                H[j] = (1.f - zg) * n + zg * H[j];
                __syncwarp();
                int o = j >> 3, k0 = (j & 7) * 4;
                const float* wr2 = WC + o * 32 + k0;
                const float* hr2 = H + k0;
                float part = wr2[0] * hr2[0];
                part = fmaf(wr2[1], hr2[1], part);
                part = fmaf(wr2[2], hr2[2], part);
                part = fmaf(wr2[3], hr2[3], part);
                #pragma unroll
                for (int off = 4; off; off >>= 1)
                    part += __shfl_xor_sync(0xffffffffu, part, off);
                float v = part + BC[o];
                float locv = __shfl_sync(0xffffffffu, v, (j & 1) * 8);
                float spv  = __shfl_sync(0xffffffffu, v, 16 + (j & 1) * 8);
                if (j < 2) {
                    float s  = fsoftplus_(spv);
                    float zt = ZB[t * 2 + j];
                    float yn = 2.f * Y[j] - Y[2 + j] + locv + s * zt;
                    out[(b * T_FUT + t) * 2 + j] = yn;
                    logdet += flogf_(s);
                    Y[2 + j] = Y[j];
                    Y[j] = yn;
                }
            }
        }
        __syncthreads();   // Y/H visible for next step
    }

    if (tid >= 128 && tid < 130) LD[tid - 128] = logdet;
    __syncthreads();
    if (tid == 0) out[B_N * T_FUT * 2 + b] = LD[0] + LD[1];
}

extern "C" void kernel_launch(void* const* d_in, const int* in_sizes, int n_in,
                              void* d_out, int out_size)
{
    const float* z    = (const float*)d_in[0];
    const float* pp   = (const float*)d_in[1];
    const float* lid  = (const float*)d_in[2];
    const float* c0w  = (const float*)d_in[3];
    const float* c0b  = (const float*)d_in[4];
    const float* c1w  = (const float*)d_in[5];
    const float* c1b  = (const float*)d_in[6];
    const float* c2w  = (const float*)d_in[7];
    const float* c2b  = (const float*)d_in[8];
    const float* c3w  = (const float*)d_in[9];
    const float* c3b  = (const float*)d_in[10];
    const float* ewih = (const float*)d_in[11];
    const float* ewhh = (const float*)d_in[12];
    const float* ebih = (const float*)d_in[13];
    const float* ebhh = (const float*)d_in[14];
    const float* dwih = (const float*)d_in[15];
    const float* dwhh = (const float*)d_in[16];
    const float* dbih = (const float*)d_in[17];
    const float* dbhh = (const float*)d_in[18];
    const float* w1   = (const float*)d_in[19];
    const float* b1   = (const float*)d_in[20];
    const float* w2   = (const float*)d_in[21];
    const float* b2   = (const float*)d_in[22];
    float* out = (float*)d_out;

    cudaFuncSetAttribute(r2p2_kernel,
                         cudaFuncAttributeMaxDynamicSharedMemorySize, SMEM_BYTES);

    r2p2_kernel<<<B_N, NT, SMEM_BYTES>>>(z, pp, lid,
        c0w, c0b, c1w, c1b, c2w, c2b, c3w, c3b,
        ewih, ewhh, ebih, ebhh, dwih, dwhh, dbih, dbhh,
        w1, b1, w2, b2, out);
}